// round 6
// baseline (speedup 1.0000x reference)
#include <cuda_runtime.h>
#include <cuda_fp16.h>
#include <cstdint>

#define FULLMASK 0xffffffffu

constexpr int SEQ = 4096, DIM = 128, BLK = 64;
constexpr int NQB = SEQ / BLK;
constexpr int NSPLIT = 4;
constexpr int JPER = (SEQ / BLK) / NSPLIT;  // 16
constexpr int NTHREADS = 256;
constexpr int H2STR = 68;   // half2 per row -> 272B row stride (conflict-free ldmatrix)
constexpr int SC_STR = 68;

// smem byte offsets
constexpr int QHI_OFF = 0;      // 64*272 = 17408 B each
constexpr int QLO_OFF = 17408;
constexpr int KHI_OFF = 34816;
constexpr int KLO_OFF = 52224;
constexpr int SC_OFF  = 69632;  // 64*68*4 = 17408 B
constexpr int SMEM_BYTES = 87040 + 256;  // ~87KB -> 2 CTA/SM

__device__ float g_partial[NSPLIT * SEQ * DIM];

__device__ __forceinline__ uint32_t smem_u32(const void* p) {
  uint32_t a;
  asm("{ .reg .u64 t; cvta.to.shared.u64 t, %1; cvt.u32.u64 %0, t; }"
      : "=r"(a) : "l"(p));
  return a;
}

#define LDMX4(R, ADDR)                                                        \
  asm volatile(                                                               \
      "ldmatrix.sync.aligned.m8n8.x4.shared.b16 {%0,%1,%2,%3}, [%4];"         \
      : "=r"((R)[0]), "=r"((R)[1]), "=r"((R)[2]), "=r"((R)[3])                \
      : "r"(ADDR))

__device__ __forceinline__ void h2split(float x, float y, uint32_t& hi, uint32_t& lo) {
  __half2 h = __floats2half2_rn(x, y);
  float2 hf = __half22float2(h);
  __half2 l = __floats2half2_rn(x - hf.x, y - hf.y);
  hi = *reinterpret_cast<uint32_t*>(&h);
  lo = *reinterpret_cast<uint32_t*>(&l);
}

__device__ __forceinline__ void mma16816(float* d, const uint32_t* a, uint32_t b0,
                                         uint32_t b1) {
  asm volatile(
      "mma.sync.aligned.m16n8k16.row.col.f32.f16.f16.f32 "
      "{%0,%1,%2,%3}, {%4,%5,%6,%7}, {%8,%9}, {%0,%1,%2,%3};"
      : "+f"(d[0]), "+f"(d[1]), "+f"(d[2]), "+f"(d[3])
      : "r"(a[0]), "r"(a[1]), "r"(a[2]), "r"(a[3]), "r"(b0), "r"(b1));
}

__device__ __forceinline__ void fill_tile_h(const float* __restrict__ g,
                                            uint32_t* hi, uint32_t* lo, int tid) {
  const float4* g4 = (const float4*)g;
#pragma unroll
  for (int it = 0; it < (BLK * DIM / 4) / NTHREADS; it++) {
    int idx = tid + it * NTHREADS;
    int row = idx >> 5, c4 = idx & 31;
    float4 x = g4[idx];
    uint32_t h01, l01, h23, l23;
    h2split(x.x, x.y, h01, l01);
    h2split(x.z, x.w, h23, l23);
    int o = row * H2STR + 2 * c4;
    *reinterpret_cast<uint2*>(hi + o) = make_uint2(h01, h23);
    *reinterpret_cast<uint2*>(lo + o) = make_uint2(l01, l23);
  }
}

__global__ void __launch_bounds__(NTHREADS, 2)
eco_attn_h2(const float* __restrict__ q, const float* __restrict__ k,
            const float* __restrict__ v) {
  extern __shared__ char smem[];
  uint32_t* qhi = (uint32_t*)(smem + QHI_OFF);
  uint32_t* qlo = (uint32_t*)(smem + QLO_OFF);
  uint32_t* khi = (uint32_t*)(smem + KHI_OFF);
  uint32_t* klo = (uint32_t*)(smem + KLO_OFF);
  float* sc = (float*)(smem + SC_OFF);

  const int split = blockIdx.x;
  const int qb = blockIdx.y;
  const int tid = threadIdx.x;
  const int lane = tid & 31;
  const int wid = tid >> 5;
  const int gid = lane >> 2;
  const int tig = lane & 3;
  const int wm = wid & 3;
  const int wn = wid >> 2;

  fill_tile_h(q + (size_t)qb * BLK * DIM, qhi, qlo, tid);
  fill_tile_h(k + (size_t)(split * JPER) * BLK * DIM, khi, klo, tid);
  __syncthreads();

  // ldmatrix base addresses (byte smem addrs)
  // A (16x16 per kk): lane row = lane&15, half-offset 8*(lane>>4)
  const uint32_t aHi =
      smem_u32(qhi) + (uint32_t)(16 * wm + (lane & 15)) * 272u + (uint32_t)(lane >> 4) * 16u;
  const uint32_t aLo = aHi + 17408u;
  // B (16 n-rows per pair): row = (lane&7) + 8*(lane>>4), half-off 8*((lane>>3)&1)
  const uint32_t bRow = (uint32_t)((lane & 7) | ((lane >> 4) << 3));
  const uint32_t bHi =
      smem_u32(khi) + (uint32_t)(32 * wn + bRow) * 272u + (uint32_t)((lane >> 3) & 1) * 16u;
  const uint32_t bLo = bHi + 17408u;

  float acc[8][4];
#pragma unroll
  for (int a = 0; a < 8; a++)
#pragma unroll
    for (int b = 0; b < 4; b++) acc[a][b] = 0.f;

  for (int jj = 0; jj < JPER; jj++) {
    const int jb = split * JPER + jj;

    // ---- prefetch next K tile (regs), latency hidden behind mma ----
    float4 pf[8];
    {
      const int jn = (jj + 1 < JPER) ? (jb + 1) : jb;
      const float4* g4 = (const float4*)(k + (size_t)jn * BLK * DIM);
#pragma unroll
      for (int it = 0; it < 8; it++) pf[it] = __ldg(g4 + tid + it * NTHREADS);
    }

    // ---- QK^T: ldmatrix fragments + 4-pass double-half mma ----
    {
      float d[4][4];
#pragma unroll
      for (int nt = 0; nt < 4; nt++)
#pragma unroll
        for (int i = 0; i < 4; i++) d[nt][i] = 0.f;

#pragma unroll
      for (int kk = 0; kk < 8; kk++) {
        const uint32_t ko = (uint32_t)kk * 32u;
        uint32_t ah[4], al[4];
        LDMX4(ah, aHi + ko);
        LDMX4(al, aLo + ko);
#pragma unroll
        for (int p = 0; p < 2; p++) {
          uint32_t bh[4], bl[4];
          LDMX4(bh, bHi + (uint32_t)p * 4352u + ko);
          LDMX4(bl, bLo + (uint32_t)p * 4352u + ko);
          // same per-(kk,nt) pass order as R5 -> bitwise identical scores
          mma16816(d[2 * p], ah, bh[0], bh[1]);
          mma16816(d[2 * p], ah, bl[0], bl[1]);
          mma16816(d[2 * p], al, bh[0], bh[1]);
          mma16816(d[2 * p], al, bl[0], bl[1]);
          mma16816(d[2 * p + 1], ah, bh[2], bh[3]);
          mma16816(d[2 * p + 1], ah, bl[2], bl[3]);
          mma16816(d[2 * p + 1], al, bh[2], bh[3]);
          mma16816(d[2 * p + 1], al, bl[2], bl[3]);
        }
      }
      const int rA = 16 * wm + gid, rB = rA + 8;
      const int cb = 32 * wn + 2 * tig;
#pragma unroll
      for (int nt = 0; nt < 4; nt++) {
        *(float2*)(sc + rA * SC_STR + cb + 8 * nt) = make_float2(d[nt][0], d[nt][1]);
        *(float2*)(sc + rB * SC_STR + cb + 8 * nt) = make_float2(d[nt][2], d[nt][3]);
      }
    }
    __syncthreads();  // scores visible; khi/klo reads done

    // ---- store prefetched next K tile ----
    if (jj + 1 < JPER) {
#pragma unroll
      for (int it = 0; it < 8; it++) {
        int idx = tid + it * NTHREADS;
        int row = idx >> 5, c4 = idx & 31;
        uint32_t h01, l01, h23, l23;
        h2split(pf[it].x, pf[it].y, h01, l01);
        h2split(pf[it].z, pf[it].w, h23, l23);
        int o = row * H2STR + 2 * c4;
        *reinterpret_cast<uint2*>(khi + o) = make_uint2(h01, h23);
        *reinterpret_cast<uint2*>(klo + o) = make_uint2(l01, l23);
      }
    }

    // ---- softmax + top-p on own rows (8wid..8wid+7); probs stay in regs ----
    int Ks[8];
    float x0[8], x1[8];
    {
      const int r0 = wid << 3;
      float mx[8], sm[8];
#pragma unroll
      for (int rr = 0; rr < 8; rr++) {
        x0[rr] = sc[(r0 + rr) * SC_STR + lane];
        x1[rr] = sc[(r0 + rr) * SC_STR + lane + 32];
        mx[rr] = fmaxf(x0[rr], x1[rr]);
      }
#pragma unroll
      for (int o = 16; o; o >>= 1)
#pragma unroll
        for (int rr = 0; rr < 8; rr++)
          mx[rr] = fmaxf(mx[rr], __shfl_xor_sync(FULLMASK, mx[rr], o));
#pragma unroll
      for (int rr = 0; rr < 8; rr++) {
        x0[rr] = __expf(x0[rr] - mx[rr]);
        x1[rr] = __expf(x1[rr] - mx[rr]);
        sm[rr] = x0[rr] + x1[rr];
      }
#pragma unroll
      for (int o = 16; o; o >>= 1)
#pragma unroll
        for (int rr = 0; rr < 8; rr++)
          sm[rr] += __shfl_xor_sync(FULLMASK, sm[rr], o);

#pragma unroll
      for (int rr = 0; rr < 8; rr++) {
        float t = 0.95f * sm[rr];
        if (!(1.0f < t)) {  // K=0 fast path (max exp == 1 exactly)
          Ks[rr] = 0;
          continue;
        }
        float w0 = x0[rr], w1 = x1[rr];
        float cum = 0.f;
        int K = 0;
        bool stop = false;
#pragma unroll 1
        for (int it = 0; it < 64 && !stop; it++) {
          float mm = fmaxf(w0, w1);
#pragma unroll
          for (int o = 16; o; o >>= 1)
            mm = fmaxf(mm, __shfl_xor_sync(FULLMASK, mm, o));
          if (mm <= 0.f) break;
          unsigned b0 = __ballot_sync(FULLMASK, w0 == mm);
          unsigned b1 = __ballot_sync(FULLMASK, w1 == mm);
          int cnt = __popc(b0) + __popc(b1);
#pragma unroll 1
          for (int i = 0; i < cnt; i++) {
            cum += mm;  // identical FP order to sorted sequential cumsum
            if (cum < t) K++;
            else { stop = true; break; }
          }
          w0 = (w0 == mm) ? 0.f : w0;
          w1 = (w1 == mm) ? 0.f : w1;
        }
        float den = ((lane < K) ? x0[rr] : 0.f) + ((lane + 32 < K) ? x1[rr] : 0.f);
#pragma unroll
        for (int o = 16; o; o >>= 1) den += __shfl_xor_sync(FULLMASK, den, o);
        float inv = 1.f / (den + 1e-8f);
        x0[rr] *= inv;
        x1[rr] *= inv;
        Ks[rr] = K;
      }
    }
    __syncthreads();  // sc free for next mma; khi/klo(jj+1) visible to all

    // ---- PV (register probs via shfl; overlaps next tile's mma across warps) ----
    {
      const float4* vg4 = (const float4*)(v + (size_t)jb * BLK * DIM);
#pragma unroll 1
      for (int rr = 0; rr < 8; rr++) {
        const int K = Ks[rr];
#pragma unroll 1
        for (int c = 0; c < K; c++) {
          float src = (c < 32) ? x0[rr] : x1[rr];
          float pc = __shfl_sync(FULLMASK, src, c & 31);
          float4 vv = __ldg(vg4 + c * 32 + lane);
          acc[rr][0] = fmaf(pc, vv.x, acc[rr][0]);
          acc[rr][1] = fmaf(pc, vv.y, acc[rr][1]);
          acc[rr][2] = fmaf(pc, vv.z, acc[rr][2]);
          acc[rr][3] = fmaf(pc, vv.w, acc[rr][3]);
        }
      }
    }
  }

  // ---- write split partials: warp rows 8wid..8wid+7, lane cols 4lane..+3 ----
  float* pbase = g_partial + ((size_t)split * SEQ + (size_t)qb * BLK) * DIM;
#pragma unroll
  for (int rr = 0; rr < 8; rr++) {
    int r = (wid << 3) + rr;
    *(float4*)(pbase + (size_t)r * DIM + 4 * lane) =
        make_float4(acc[rr][0], acc[rr][1], acc[rr][2], acc[rr][3]);
  }
}

__global__ void reduce_partials(float* __restrict__ out) {
  const int idx = blockIdx.x * blockDim.x + threadIdx.x;
  const float4* p = (const float4*)g_partial;
  float4 s = p[idx];
#pragma unroll
  for (int sp = 1; sp < NSPLIT; sp++) {
    float4 t = p[(size_t)sp * (SEQ * DIM / 4) + idx];
    s.x += t.x; s.y += t.y; s.z += t.z; s.w += t.w;
  }
  ((float4*)out)[idx] = s;
}

extern "C" void kernel_launch(void* const* d_in, const int* in_sizes, int n_in,
                              void* d_out, int out_size) {
  const float* q = (const float*)d_in[0];
  const float* k = (const float*)d_in[1];
  const float* v = (const float*)d_in[2];
  float* out = (float*)d_out;

  cudaFuncSetAttribute(eco_attn_h2, cudaFuncAttributeMaxDynamicSharedMemorySize,
                       SMEM_BYTES);
  dim3 grid(NSPLIT, NQB);
  eco_attn_h2<<<grid, NTHREADS, SMEM_BYTES>>>(q, k, v);
  reduce_partials<<<(SEQ * DIM / 4) / 256, 256>>>(out);
}

// round 7
// speedup vs baseline: 1.1450x; 1.1450x over previous
#include <cuda_runtime.h>
#include <cuda_fp16.h>
#include <cstdint>

#define FULLMASK 0xffffffffu

constexpr int SEQ = 4096, DIM = 128, BLK = 64;
constexpr int NQB = SEQ / BLK;
constexpr int NSPLIT = 4;
constexpr int JPER = (SEQ / BLK) / NSPLIT;  // 16
constexpr int NTHREADS = 256;
constexpr int H2STR = 68;   // half2 per row; 68 % 32 == 4 -> fragment LDS conflict-free
constexpr int SC_STR = 68;  // floats per score row

// smem byte offsets
constexpr int QHI_OFF = 0;        // 64*68*4 = 17408 B each
constexpr int QLO_OFF = 17408;
constexpr int KHI_OFF = 34816;
constexpr int KLO_OFF = 52224;
constexpr int SC0_OFF = 69632;    // score buffer 0
constexpr int SC1_OFF = 87040;    // score buffer 1
constexpr int KC_OFF  = 104448;   // 64 ints
constexpr int SMEM_BYTES = 104448 + 512;  // 104960 (x2 CTA = 205KB < 228KB)

__device__ float g_partial[NSPLIT * SEQ * DIM];

__device__ __forceinline__ void h2split(float x, float y, uint32_t& hi, uint32_t& lo) {
  __half2 h = __floats2half2_rn(x, y);
  float2 hf = __half22float2(h);
  __half2 l = __floats2half2_rn(x - hf.x, y - hf.y);
  hi = *reinterpret_cast<uint32_t*>(&h);
  lo = *reinterpret_cast<uint32_t*>(&l);
}

__device__ __forceinline__ void mma16816(float* d, uint32_t a0, uint32_t a1,
                                         uint32_t a2, uint32_t a3, uint32_t b0,
                                         uint32_t b1) {
  asm volatile(
      "mma.sync.aligned.m16n8k16.row.col.f32.f16.f16.f32 "
      "{%0,%1,%2,%3}, {%4,%5,%6,%7}, {%8,%9}, {%0,%1,%2,%3};"
      : "+f"(d[0]), "+f"(d[1]), "+f"(d[2]), "+f"(d[3])
      : "r"(a0), "r"(a1), "r"(a2), "r"(a3), "r"(b0), "r"(b1));
}

__device__ __forceinline__ void fill_tile_h(const float* __restrict__ g,
                                            uint32_t* hi, uint32_t* lo, int tid) {
  const float4* g4 = (const float4*)g;
#pragma unroll
  for (int it = 0; it < (BLK * DIM / 4) / NTHREADS; it++) {
    int idx = tid + it * NTHREADS;
    int row = idx >> 5, c4 = idx & 31;
    float4 x = g4[idx];
    uint32_t h01, l01, h23, l23;
    h2split(x.x, x.y, h01, l01);
    h2split(x.z, x.w, h23, l23);
    int o = row * H2STR + 2 * c4;
    *reinterpret_cast<uint2*>(hi + o) = make_uint2(h01, h23);
    *reinterpret_cast<uint2*>(lo + o) = make_uint2(l01, l23);
  }
}

__global__ void __launch_bounds__(NTHREADS, 2)
eco_attn_h2(const float* __restrict__ q, const float* __restrict__ k,
            const float* __restrict__ v) {
  extern __shared__ char smem[];
  uint32_t* qhi = (uint32_t*)(smem + QHI_OFF);
  uint32_t* qlo = (uint32_t*)(smem + QLO_OFF);
  uint32_t* khi = (uint32_t*)(smem + KHI_OFF);
  uint32_t* klo = (uint32_t*)(smem + KLO_OFF);
  float* sc0 = (float*)(smem + SC0_OFF);
  float* sc1 = (float*)(smem + SC1_OFF);
  int* kcnt = (int*)(smem + KC_OFF);

  const int split = blockIdx.x;
  const int qb = blockIdx.y;
  const int tid = threadIdx.x;
  const int lane = tid & 31;
  const int wid = tid >> 5;
  const int gid = lane >> 2;
  const int tig = lane & 3;
  const int wm = wid & 3;
  const int wn = wid >> 2;
  const int ty = tid >> 4;
  const int tx = tid & 15;

  fill_tile_h(q + (size_t)qb * BLK * DIM, qhi, qlo, tid);
  fill_tile_h(k + (size_t)(split * JPER) * BLK * DIM, khi, klo, tid);
  __syncthreads();

  float acc[4][8];
#pragma unroll
  for (int a = 0; a < 4; a++)
#pragma unroll
    for (int b = 0; b < 8; b++) acc[a][b] = 0.f;

  const int arow0 = (16 * wm + gid) * H2STR + tig;
  const int arow1 = arow0 + 8 * H2STR;
  const int brow = (32 * wn + gid) * H2STR + tig;

  for (int jj = 0; jj < JPER; jj++) {
    const int jb = split * JPER + jj;
    float* scb = (jj & 1) ? sc1 : sc0;

    // ---- prefetch next K tile into registers (latency hidden behind mma) ----
    float4 pf[8];
    {
      const int jn = (jj + 1 < JPER) ? (jb + 1) : jb;
      const float4* g4 = (const float4*)(k + (size_t)jn * BLK * DIM);
#pragma unroll
      for (int it = 0; it < 8; it++) pf[it] = __ldg(g4 + tid + it * NTHREADS);
    }

    // ---- QK^T: 4-pass double-half mma ----
    {
      float d[4][4];
#pragma unroll
      for (int nt = 0; nt < 4; nt++)
#pragma unroll
        for (int i = 0; i < 4; i++) d[nt][i] = 0.f;

#pragma unroll
      for (int kk = 0; kk < 8; kk++) {
        const int ko = 8 * kk;
        uint32_t ah0 = qhi[arow0 + ko], ah1 = qhi[arow1 + ko];
        uint32_t ah2 = qhi[arow0 + ko + 4], ah3 = qhi[arow1 + ko + 4];
        uint32_t al0 = qlo[arow0 + ko], al1 = qlo[arow1 + ko];
        uint32_t al2 = qlo[arow0 + ko + 4], al3 = qlo[arow1 + ko + 4];
#pragma unroll
        for (int nt = 0; nt < 4; nt++) {
          const int bo = brow + nt * 8 * H2STR + ko;
          uint32_t bh0 = khi[bo], bh1 = khi[bo + 4];
          uint32_t bl0 = klo[bo], bl1 = klo[bo + 4];
          mma16816(d[nt], ah0, ah1, ah2, ah3, bh0, bh1);
          mma16816(d[nt], ah0, ah1, ah2, ah3, bl0, bl1);
          mma16816(d[nt], al0, al1, al2, al3, bh0, bh1);
          mma16816(d[nt], al0, al1, al2, al3, bl0, bl1);
        }
      }
      const int rA = 16 * wm + gid, rB = rA + 8;
      const int cb = 32 * wn + 2 * tig;
#pragma unroll
      for (int nt = 0; nt < 4; nt++) {
        *(float2*)(scb + rA * SC_STR + cb + 8 * nt) = make_float2(d[nt][0], d[nt][1]);
        *(float2*)(scb + rB * SC_STR + cb + 8 * nt) = make_float2(d[nt][2], d[nt][3]);
      }
    }
    __syncthreads();  // scores visible; khi/klo no longer read

    // ---- store prefetched next K tile ----
    if (jj + 1 < JPER) {
#pragma unroll
      for (int it = 0; it < 8; it++) {
        int idx = tid + it * NTHREADS;
        int row = idx >> 5, c4 = idx & 31;
        uint32_t h01, l01, h23, l23;
        h2split(pf[it].x, pf[it].y, h01, l01);
        h2split(pf[it].z, pf[it].w, h23, l23);
        int o = row * H2STR + 2 * c4;
        *reinterpret_cast<uint2*>(khi + o) = make_uint2(h01, h23);
        *reinterpret_cast<uint2*>(klo + o) = make_uint2(l01, l23);
      }
    }

    // ---- softmax: batched reductions + group-of-4 batched extract-max ----
    {
      const int r0 = wid << 3;
      float x0[8], x1[8], mx[8], sm[8];
      int K8[8];
#pragma unroll
      for (int rr = 0; rr < 8; rr++) {
        x0[rr] = scb[(r0 + rr) * SC_STR + lane];
        x1[rr] = scb[(r0 + rr) * SC_STR + lane + 32];
        mx[rr] = fmaxf(x0[rr], x1[rr]);
      }
#pragma unroll
      for (int o = 16; o; o >>= 1)
#pragma unroll
        for (int rr = 0; rr < 8; rr++)
          mx[rr] = fmaxf(mx[rr], __shfl_xor_sync(FULLMASK, mx[rr], o));
#pragma unroll
      for (int rr = 0; rr < 8; rr++) {
        x0[rr] = __expf(x0[rr] - mx[rr]);
        x1[rr] = __expf(x1[rr] - mx[rr]);
        sm[rr] = x0[rr] + x1[rr];
      }
#pragma unroll
      for (int o = 16; o; o >>= 1)
#pragma unroll
        for (int rr = 0; rr < 8; rr++)
          sm[rr] += __shfl_xor_sync(FULLMASK, sm[rr], o);

      // ---- extract-max, 4 rows interleaved (same per-row FP order as before) ----
#pragma unroll
      for (int g = 0; g < 2; g++) {
        float w0g[4], w1g[4], cumg[4], tg[4];
        int Kg[4];
        bool dn[4];
#pragma unroll
        for (int i = 0; i < 4; i++) {
          const int rr = 4 * g + i;
          tg[i] = 0.95f * sm[rr];
          w0g[i] = x0[rr];
          w1g[i] = x1[rr];
          cumg[i] = 0.f;
          Kg[i] = 0;
          dn[i] = !(1.0f < tg[i]);  // K=0 fast path (max exp == 1 exactly)
        }
#pragma unroll 1
        for (int it = 0; it < 64; it++) {
          if (dn[0] && dn[1] && dn[2] && dn[3]) break;
          float mm[4];
#pragma unroll
          for (int i = 0; i < 4; i++) mm[i] = dn[i] ? 1.f : fmaxf(w0g[i], w1g[i]);
#pragma unroll
          for (int o = 16; o; o >>= 1)
#pragma unroll
            for (int i = 0; i < 4; i++)
              mm[i] = fmaxf(mm[i], __shfl_xor_sync(FULLMASK, mm[i], o));
#pragma unroll
          for (int i = 0; i < 4; i++) {
            if (dn[i]) continue;  // warp-uniform predicate
            if (mm[i] <= 0.f) { dn[i] = true; continue; }
            unsigned b0 = __ballot_sync(FULLMASK, w0g[i] == mm[i]);
            unsigned b1 = __ballot_sync(FULLMASK, w1g[i] == mm[i]);
            int cnt = __popc(b0) + __popc(b1);
#pragma unroll 1
            for (int c2 = 0; c2 < cnt; c2++) {
              cumg[i] += mm[i];  // identical FP order to sorted sequential cumsum
              if (cumg[i] < tg[i]) Kg[i]++;
              else { dn[i] = true; break; }
            }
            w0g[i] = (w0g[i] == mm[i]) ? 0.f : w0g[i];
            w1g[i] = (w1g[i] == mm[i]) ? 0.f : w1g[i];
          }
        }
#pragma unroll
        for (int i = 0; i < 4; i++) K8[4 * g + i] = Kg[i];
      }

      // ---- batched denominator reduce over all 8 rows ----
      float den[8];
#pragma unroll
      for (int rr = 0; rr < 8; rr++)
        den[rr] = ((lane < K8[rr]) ? x0[rr] : 0.f) +
                  ((lane + 32 < K8[rr]) ? x1[rr] : 0.f);
#pragma unroll
      for (int o = 16; o; o >>= 1)
#pragma unroll
        for (int rr = 0; rr < 8; rr++)
          den[rr] += __shfl_xor_sync(FULLMASK, den[rr], o);

#pragma unroll
      for (int rr = 0; rr < 8; rr++) {
        float* srow = scb + (r0 + rr) * SC_STR;
        float inv = 1.f / (den[rr] + 1e-8f);
        srow[lane] = (lane < K8[rr]) ? x0[rr] * inv : 0.f;
        srow[lane + 32] = (lane + 32 < K8[rr]) ? x1[rr] * inv : 0.f;
        if (lane == 0) kcnt[r0 + rr] = K8[rr];
      }
    }
    __syncthreads();  // probs + kcnt + next K tile visible

    // ---- PV: rows ty+16rr, cols 8tx..8tx+7 ----
    int kmax = kcnt[ty];
    kmax = max(kmax, kcnt[ty + 16]);
    kmax = max(kmax, kcnt[ty + 32]);
    kmax = max(kmax, kcnt[ty + 48]);
    const float4* vg = (const float4*)(v + (size_t)jb * BLK * DIM);
#pragma unroll 1
    for (int c = 0; c < kmax; c++) {
      float wv[4];
      wv[0] = scb[(ty)*SC_STR + c];
      wv[1] = scb[(ty + 16) * SC_STR + c];
      wv[2] = scb[(ty + 32) * SC_STR + c];
      wv[3] = scb[(ty + 48) * SC_STR + c];
      float4 va = __ldg(vg + c * 32 + (tx << 1));
      float4 vb = __ldg(vg + c * 32 + (tx << 1) + 1);
      float vv[8] = {va.x, va.y, va.z, va.w, vb.x, vb.y, vb.z, vb.w};
#pragma unroll
      for (int rr = 0; rr < 4; rr++)
#pragma unroll
        for (int cc = 0; cc < 8; cc++) acc[rr][cc] = fmaf(wv[rr], vv[cc], acc[rr][cc]);
    }
    // PV(jj) overlaps next iter's mma/scores (other sc buffer); kcnt overwrite
    // is fenced by next iter's first __syncthreads.
  }

  float* pbase = g_partial + ((size_t)split * SEQ + (size_t)qb * BLK) * DIM;
#pragma unroll
  for (int rr = 0; rr < 4; rr++) {
    int r = ty + 16 * rr;
    float4* dst = (float4*)(pbase + (size_t)r * DIM + (tx << 3));
    dst[0] = make_float4(acc[rr][0], acc[rr][1], acc[rr][2], acc[rr][3]);
    dst[1] = make_float4(acc[rr][4], acc[rr][5], acc[rr][6], acc[rr][7]);
  }
}

__global__ void reduce_partials(float* __restrict__ out) {
  const int idx = blockIdx.x * blockDim.x + threadIdx.x;
  const float4* p = (const float4*)g_partial;
  float4 s = p[idx];
#pragma unroll
  for (int sp = 1; sp < NSPLIT; sp++) {
    float4 t = p[(size_t)sp * (SEQ * DIM / 4) + idx];
    s.x += t.x; s.y += t.y; s.z += t.z; s.w += t.w;
  }
  ((float4*)out)[idx] = s;
}

extern "C" void kernel_launch(void* const* d_in, const int* in_sizes, int n_in,
                              void* d_out, int out_size) {
  const float* q = (const float*)d_in[0];
  const float* k = (const float*)d_in[1];
  const float* v = (const float*)d_in[2];
  float* out = (float*)d_out;

  cudaFuncSetAttribute(eco_attn_h2, cudaFuncAttributeMaxDynamicSharedMemorySize,
                       SMEM_BYTES);
  dim3 grid(NSPLIT, NQB);
  eco_attn_h2<<<grid, NTHREADS, SMEM_BYTES>>>(q, k, v);
  reduce_partials<<<(SEQ * DIM / 4) / 256, 256>>>(out);
}